// round 7
// baseline (speedup 1.0000x reference)
#include <cuda_runtime.h>
#include <cuda_bf16.h>
#include <cstdint>

#define NN 512      // tokens
#define DN 256      // d_node
#define DE 128      // d_edge
#define DH 32       // d_head
#define LN_EPS 1e-5f
#define NGRP 37     // 37 groups x 4 m-tiles = 148 blocks (1/SM)

// Scratch (device globals: no allocation allowed)
__device__ float g_left[NN * DH];
__device__ float g_right[NN * DH];
__device__ float g_T[NN * DH * DE];   // [n][j][e] = [512][32][128] fp32

// ---------------- bf16 hi/lo pack ----------------
__device__ __forceinline__ uint32_t pack_bf2(float x0, float x1, uint32_t& lo_pack) {
    __nv_bfloat16 h0 = __float2bfloat16(x0);
    __nv_bfloat16 h1 = __float2bfloat16(x1);
    __nv_bfloat16 l0 = __float2bfloat16(x0 - __bfloat162float(h0));
    __nv_bfloat16 l1 = __float2bfloat16(x1 - __bfloat162float(h1));
    uint32_t hp = (uint32_t)__bfloat16_as_ushort(h0) |
                  ((uint32_t)__bfloat16_as_ushort(h1) << 16);
    lo_pack = (uint32_t)__bfloat16_as_ushort(l0) |
              ((uint32_t)__bfloat16_as_ushort(l1) << 16);
    return hp;
}

// mma.sync m16n8k16 row.col bf16 -> f32 accumulate (baseline PTX, sm_80+)
__device__ __forceinline__ void mma16816(float* c, const uint32_t* a,
                                         uint32_t b0, uint32_t b1) {
    asm volatile(
        "mma.sync.aligned.m16n8k16.row.col.f32.bf16.bf16.f32 "
        "{%0,%1,%2,%3}, {%4,%5,%6,%7}, {%8,%9}, {%0,%1,%2,%3};"
        : "+f"(c[0]), "+f"(c[1]), "+f"(c[2]), "+f"(c[3])
        : "r"(a[0]), "r"(a[1]), "r"(a[2]), "r"(a[3]), "r"(b0), "r"(b1));
}

// ---------------- P1: LayerNorm + left/right projections ----------------
__global__ void p1_kernel(const float* __restrict__ node,
                          const float* __restrict__ ln_w,
                          const float* __restrict__ ln_b,
                          const float* __restrict__ wl,
                          const float* __restrict__ bl,
                          const float* __restrict__ wr,
                          const float* __restrict__ br) {
    __shared__ float xs[DN];
    __shared__ float2 red[8];
    __shared__ float ps[4][64];

    int n = blockIdx.x;
    int tid = threadIdx.x;
    float v = node[n * DN + tid];

    float s = v, q = v * v;
    #pragma unroll
    for (int o = 16; o; o >>= 1) {
        s += __shfl_xor_sync(0xffffffffu, s, o);
        q += __shfl_xor_sync(0xffffffffu, q, o);
    }
    if ((tid & 31) == 0) red[tid >> 5] = make_float2(s, q);
    __syncthreads();
    float S = 0.f, Q = 0.f;
    #pragma unroll
    for (int i = 0; i < 8; i++) { S += red[i].x; Q += red[i].y; }
    float mu = S * (1.f / 256.f);
    float var = Q * (1.f / 256.f) - mu * mu;
    float rstd = rsqrtf(var + LN_EPS);

    xs[tid] = (v - mu) * rstd * ln_w[tid] + ln_b[tid];
    __syncthreads();

    int h = tid & 31;
    int sel = (tid >> 5) & 1;
    int part = tid >> 6;
    const float* __restrict__ w = sel ? wr : wl;
    int k0 = part * 64;
    float a0 = 0.f, a1 = 0.f, a2 = 0.f, a3 = 0.f;
    #pragma unroll 4
    for (int k = 0; k < 64; k += 4) {
        a0 += xs[k0 + k + 0] * w[(k0 + k + 0) * DH + h];
        a1 += xs[k0 + k + 1] * w[(k0 + k + 1) * DH + h];
        a2 += xs[k0 + k + 2] * w[(k0 + k + 2) * DH + h];
        a3 += xs[k0 + k + 3] * w[(k0 + k + 3) * DH + h];
    }
    ps[part][sel * 32 + h] = (a0 + a1) + (a2 + a3);
    __syncthreads();

    if (tid < 64) {
        float r = ps[0][tid] + ps[1][tid] + ps[2][tid] + ps[3][tid];
        if (tid < 32) g_left[n * DH + tid] = r + bl[tid];
        else          g_right[n * DH + (tid - 32)] = r + br[tid - 32];
    }
}

// ---------------- P2: T = left @ w_out (viewed [32][4096]) ----------------
__global__ void p2_kernel(const float* __restrict__ w_out) {
    __shared__ float As[32 * 32];

    int nb = blockIdx.y * 32;
    int cb = blockIdx.x * 128;
    int tid = threadIdx.x;

    {
        int row = tid >> 3, qq = tid & 7;
        *(float4*)&As[row * 32 + qq * 4] =
            *(const float4*)(g_left + (nb + row) * DH + qq * 4);
    }
    __syncthreads();

    int col = cb + (tid & 127);
    int nset = tid >> 7;
    float acc[16];
    #pragma unroll
    for (int r = 0; r < 16; r++) acc[r] = 0.f;

    #pragma unroll 4
    for (int i = 0; i < 32; i++) {
        float b = w_out[i * 4096 + col];
        #pragma unroll
        for (int r = 0; r < 16; r++)
            acc[r] += As[(nset * 16 + r) * 32 + i] * b;
    }

    #pragma unroll
    for (int r = 0; r < 16; r++)
        g_T[(nb + nset * 16 + r) * (DH * DE) + col] = acc[r];
}

// ---------------- Main kernel: out = edge + b_out + right @ T (HMMA) ------
// Persistent 148 blocks x 512 threads. Per block: m-tile fixed, ~14 n values.
// Warp tile: 16m x 64e. A (right) bf16 hi/lo fragments in registers (once).
// B (T[n]) staged to smem transposed [e][j] pre-packed bf16 hi/lo, pitch 17
// words (conflict-free staging), double-buffered. 3 products per k-tile:
// AhiBhi + AhiBlo + AloBhi (fp32 accum) -> rel err ~1e-5.
#define BPITCH 17
__global__ void __launch_bounds__(512)
outk_kernel(const float* __restrict__ edge,
            const float* __restrict__ b_out,
            float* __restrict__ out) {
    __shared__ uint32_t sBh[2][128 * BPITCH];
    __shared__ uint32_t sBl[2][128 * BPITCH];

    int tid = threadIdx.x;
    int w = tid >> 5, lane = tid & 31;
    int g = lane >> 2, tig = lane & 3;
    int m_tile = blockIdx.x & 3;
    int grp = blockIdx.x >> 2;
    int n0 = (grp * NN) / NGRP;
    int n1 = ((grp + 1) * NN) / NGRP;
    int m_base = m_tile * 128;

    int m0 = (w >> 1) * 16;          // warp's 16 m rows within tile
    int ehalf = (w & 1) * 64;        // warp's 64 e columns

    // ---- A fragments (once): right[m_base+m0 .. +16][0..32), hi/lo ----
    uint32_t Ah[2][4], Al[2][4];
    {
        const float* r0 = g_right + (m_base + m0 + g) * DH;
        const float* r8 = r0 + 8 * DH;
        #pragma unroll
        for (int kt = 0; kt < 2; kt++) {
            int c0 = 2 * tig + 16 * kt;
            float2 v00 = *(const float2*)(r0 + c0);
            float2 v10 = *(const float2*)(r8 + c0);
            float2 v01 = *(const float2*)(r0 + c0 + 8);
            float2 v11 = *(const float2*)(r8 + c0 + 8);
            Ah[kt][0] = pack_bf2(v00.x, v00.y, Al[kt][0]);
            Ah[kt][1] = pack_bf2(v10.x, v10.y, Al[kt][1]);
            Ah[kt][2] = pack_bf2(v01.x, v01.y, Al[kt][2]);
            Ah[kt][3] = pack_bf2(v11.x, v11.y, Al[kt][3]);
        }
    }

    // ---- bias (once): per et, cols (ehalf+8et+2tig, +1) ----
    float2 bias[8];
    {
        const float* bp = b_out + ehalf + 2 * tig;
        #pragma unroll
        for (int et = 0; et < 8; et++) bias[et] = *(const float2*)(bp + 8 * et);
    }

    // ---- staging lambda params: e = tid&127, jp block = (tid>>7)*4 ----
    int se = tid & 127;
    int sq = (tid >> 7) * 4;

    // stage T[n0] into buf 0
    {
        const float* tn = g_T + (size_t)n0 * (DH * DE);
        #pragma unroll
        for (int r = 0; r < 4; r++) {
            int jp = sq + r;
            float x0 = __ldg(tn + (2 * jp) * DE + se);
            float x1 = __ldg(tn + (2 * jp + 1) * DE + se);
            uint32_t lp, hp = pack_bf2(x0, x1, lp);
            sBh[0][se * BPITCH + jp] = hp;
            sBl[0][se * BPITCH + jp] = lp;
        }
    }
    __syncthreads();

    int buf = 0;
    for (int n = n0; n < n1; n++, buf ^= 1) {
        // stage T[n+1] into other buffer (overlaps mma below across warps)
        if (n + 1 < n1) {
            const float* tn = g_T + (size_t)(n + 1) * (DH * DE);
            #pragma unroll
            for (int r = 0; r < 4; r++) {
                int jp = sq + r;
                float x0 = __ldg(tn + (2 * jp) * DE + se);
                float x1 = __ldg(tn + (2 * jp + 1) * DE + se);
                uint32_t lp, hp = pack_bf2(x0, x1, lp);
                sBh[buf ^ 1][se * BPITCH + jp] = hp;
                sBl[buf ^ 1][se * BPITCH + jp] = lp;
            }
        }

        // issue edge loads (consumed only in epilogue -> hidden under mma)
        float2 ev0[8], ev1[8];
        {
            const float* eb = edge + ((size_t)n * NN + m_base + m0 + g) * DE
                              + ehalf + 2 * tig;
            #pragma unroll
            for (int et = 0; et < 8; et++) {
                ev0[et] = __ldcs((const float2*)(eb + 8 * et));
                ev1[et] = __ldcs((const float2*)(eb + 8 * et + 8 * DE));
            }
        }

        // accumulators init from bias (rows g and g+8 share the same cols)
        float acc[8][4];
        #pragma unroll
        for (int et = 0; et < 8; et++) {
            acc[et][0] = bias[et].x; acc[et][1] = bias[et].y;
            acc[et][2] = bias[et].x; acc[et][3] = bias[et].y;
        }

        // mma loop: 8 et x 2 kt x 3 products = 48 HMMA
        const uint32_t* bh = sBh[buf];
        const uint32_t* bl = sBl[buf];
        #pragma unroll
        for (int et = 0; et < 8; et++) {
            int erow = (ehalf + 8 * et + g) * BPITCH;
            #pragma unroll
            for (int kt = 0; kt < 2; kt++) {
                uint32_t bh0 = bh[erow + tig + 8 * kt];
                uint32_t bh1 = bh[erow + tig + 4 + 8 * kt];
                uint32_t bl0 = bl[erow + tig + 8 * kt];
                uint32_t bl1 = bl[erow + tig + 4 + 8 * kt];
                mma16816(acc[et], Ah[kt], bh0, bh1);
                mma16816(acc[et], Ah[kt], bl0, bl1);
                mma16816(acc[et], Al[kt], bh0, bh1);
            }
        }

        // epilogue: add edge, streaming stores (sector-complete float2)
        {
            float* ob = out + ((size_t)n * NN + m_base + m0 + g) * DE
                        + ehalf + 2 * tig;
            #pragma unroll
            for (int et = 0; et < 8; et++) {
                __stcs((float2*)(ob + 8 * et),
                       make_float2(acc[et][0] + ev0[et].x, acc[et][1] + ev0[et].y));
                __stcs((float2*)(ob + 8 * et + 8 * DE),
                       make_float2(acc[et][2] + ev1[et].x, acc[et][3] + ev1[et].y));
            }
        }

        __syncthreads();   // buf^1 staged for next iter; buf reads complete
    }
}

// ---------------- launch ----------------
extern "C" void kernel_launch(void* const* d_in, const int* in_sizes, int n_in,
                              void* d_out, int out_size) {
    const float* node   = (const float*)d_in[0];
    const float* edge   = (const float*)d_in[1];
    const float* ln_w   = (const float*)d_in[2];
    const float* ln_b   = (const float*)d_in[3];
    const float* w_left = (const float*)d_in[4];
    const float* b_left = (const float*)d_in[5];
    const float* w_right= (const float*)d_in[6];
    const float* b_right= (const float*)d_in[7];
    const float* w_out  = (const float*)d_in[8];
    const float* b_out  = (const float*)d_in[9];
    float* out = (float*)d_out;

    p1_kernel<<<NN, 256>>>(node, ln_w, ln_b, w_left, b_left, w_right, b_right);
    p2_kernel<<<dim3(32, 16), 256>>>(w_out);
    outk_kernel<<<NGRP * 4, 512>>>(edge, b_out, out);
}